// round 3
// baseline (speedup 1.0000x reference)
#include <cuda_runtime.h>
#include <cuda_bf16.h>
#include <cstdint>

// Problem constants
#define M_ROWS 224      // B*N = 32*7
#define K_DIM  49152    // 768*64
#define PRED   336
#define NBANDS 4
#define NCOLS  1344     // NBANDS*PRED
// GEMM tiling
#define BN       96
#define NTILES   14     // 1344/96
#define SPLITS   24
#define KCHUNK   2048   // 49152/24
#define KT       16
#define KITERS   128    // KCHUNK/KT
#define THREADS_G 448   // 14 warps, warp tile 16x96

// Split-K scratch (deterministic reduction; no atomics)
__device__ float g_part[SPLITS * M_ROWS * NCOLS];

// db4 reconstruction filters (REC_LO = reversed DEC_LO; REC_HI = QMF)
__constant__ float c_RL[8] = {
     0.23037781330885523f,  0.7148465705525415f,   0.6308807679295904f,
    -0.02798376941698385f, -0.18703481171888114f,  0.030841381835986965f,
     0.032883011666982945f, -0.010597401784997278f };
__constant__ float c_RH[8] = {
     0.010597401784997278f, 0.032883011666982945f, -0.030841381835986965f,
    -0.18703481171888114f,  0.02798376941698385f,   0.6308807679295904f,
    -0.7148465705525415f,   0.23037781330885523f };

__device__ __forceinline__ uint32_t ld_b32(const __nv_bfloat16* p) {
    return *reinterpret_cast<const uint32_t*>(p);
}

#define MMA_BF16(C, A0, A1, A2, A3, B0, B1)                                  \
  asm volatile(                                                              \
      "mma.sync.aligned.m16n8k16.row.col.f32.bf16.bf16.f32 "                 \
      "{%0,%1,%2,%3}, {%4,%5,%6,%7}, {%8,%9}, {%0,%1,%2,%3};\n"              \
      : "+f"(C[0]), "+f"(C[1]), "+f"(C[2]), "+f"(C[3])                       \
      : "r"(A0), "r"(A1), "r"(A2), "r"(A3), "r"(B0), "r"(B1))

// ---------------------------------------------------------------------------
// GEMM: C[224,1344] = X[224,49152] @ Wcat[49152,1344]  (split-K partials)
// fp32 inputs split into bf16 hi/lo in-kernel; 3 HMMA products per tile
// (hi*hi + hi*lo + lo*hi), fp32 accumulation.
// ---------------------------------------------------------------------------
__global__ __launch_bounds__(THREADS_G)
void gemm_split(const float* __restrict__ X, const float* __restrict__ W)
{
    // row pad 24 halves (48B = 12 words) -> conflict-free b32 fragment loads
    __shared__ __nv_bfloat16 sAh[M_ROWS][24];
    __shared__ __nv_bfloat16 sAl[M_ROWS][24];
    __shared__ __nv_bfloat16 sBh[BN][24];
    __shared__ __nv_bfloat16 sBl[BN][24];

    const int t     = threadIdx.x;
    const int n0    = blockIdx.x * BN;
    const int split = blockIdx.y;
    const int kbase = split * KCHUNK;

    // ---- A loader: 2 threads per row, 8 floats each
    const int arow  = t >> 1;
    const int ahalf = (t & 1) * 8;
    const float* aptr = X + (size_t)arow * K_DIM + kbase + ahalf;

    // ---- B loader: 16x96 tile = 1536 elems over 448 threads (<=4 each)
    int  br[4], bj[4];
    bool bv[4];
    size_t bbase[4];
    #pragma unroll
    for (int i = 0; i < 4; ++i) {
        int idx = t + i * THREADS_G;
        bv[i] = (idx < KT * BN);
        int r = bv[i] ? (idx / BN) : 0;
        int j = bv[i] ? (idx - r * BN) : 0;
        int c = n0 + j;
        int band = c / PRED;
        int p = c - band * PRED;
        br[i] = r; bj[i] = j;
        bbase[i] = ((size_t)band * K_DIM + (size_t)(kbase + r)) * PRED + p;
    }

    float va[8], vb[4];
    // prologue: load kt = 0 into registers
    {
        const float4 u0 = *reinterpret_cast<const float4*>(aptr);
        const float4 u1 = *reinterpret_cast<const float4*>(aptr + 4);
        va[0] = u0.x; va[1] = u0.y; va[2] = u0.z; va[3] = u0.w;
        va[4] = u1.x; va[5] = u1.y; va[6] = u1.z; va[7] = u1.w;
        #pragma unroll
        for (int i = 0; i < 4; ++i) vb[i] = bv[i] ? W[bbase[i]] : 0.f;
    }

    const int lane    = t & 31;
    const int warp    = t >> 5;
    const int rowbase = warp * 16;       // warp tile: rows [16w,16w+16), cols [n0,n0+96)
    const int rA      = lane >> 2;
    const int cA      = (lane & 3) * 2;

    float acc[12][4];
    #pragma unroll
    for (int nt = 0; nt < 12; ++nt) {
        acc[nt][0] = 0.f; acc[nt][1] = 0.f; acc[nt][2] = 0.f; acc[nt][3] = 0.f;
    }

    for (int kt = 0; kt < KITERS; ++kt) {
        // convert current registers -> smem (bf16 hi/lo)
        #pragma unroll
        for (int i = 0; i < 8; ++i) {
            float v = va[i];
            __nv_bfloat16 h = __float2bfloat16(v);
            __nv_bfloat16 l = __float2bfloat16(v - __bfloat162float(h));
            sAh[arow][ahalf + i] = h;
            sAl[arow][ahalf + i] = l;
        }
        #pragma unroll
        for (int i = 0; i < 4; ++i) {
            if (bv[i]) {
                float v = vb[i];
                __nv_bfloat16 h = __float2bfloat16(v);
                __nv_bfloat16 l = __float2bfloat16(v - __bfloat162float(h));
                sBh[bj[i]][br[i]] = h;   // stored transposed: [n][k]
                sBl[bj[i]][br[i]] = l;
            }
        }
        __syncthreads();

        // prefetch next k-tile into registers (overlaps with compute)
        if (kt + 1 < KITERS) {
            const float* ap = aptr + (kt + 1) * KT;
            const float4 u0 = *reinterpret_cast<const float4*>(ap);
            const float4 u1 = *reinterpret_cast<const float4*>(ap + 4);
            va[0] = u0.x; va[1] = u0.y; va[2] = u0.z; va[3] = u0.w;
            va[4] = u1.x; va[5] = u1.y; va[6] = u1.z; va[7] = u1.w;
            const size_t koff = (size_t)(kt + 1) * KT * PRED;
            #pragma unroll
            for (int i = 0; i < 4; ++i)
                vb[i] = bv[i] ? W[bbase[i] + koff] : 0.f;
        }

        // A fragments (m16n8k16 row-major layout)
        const uint32_t ah0 = ld_b32(&sAh[rowbase + rA    ][cA    ]);
        const uint32_t ah1 = ld_b32(&sAh[rowbase + rA + 8][cA    ]);
        const uint32_t ah2 = ld_b32(&sAh[rowbase + rA    ][cA + 8]);
        const uint32_t ah3 = ld_b32(&sAh[rowbase + rA + 8][cA + 8]);
        const uint32_t al0 = ld_b32(&sAl[rowbase + rA    ][cA    ]);
        const uint32_t al1 = ld_b32(&sAl[rowbase + rA + 8][cA    ]);
        const uint32_t al2 = ld_b32(&sAl[rowbase + rA    ][cA + 8]);
        const uint32_t al3 = ld_b32(&sAl[rowbase + rA + 8][cA + 8]);

        #pragma unroll
        for (int nt = 0; nt < 12; ++nt) {
            const int cn = nt * 8 + rA;
            const uint32_t bh0 = ld_b32(&sBh[cn][cA    ]);
            const uint32_t bh1 = ld_b32(&sBh[cn][cA + 8]);
            const uint32_t bl0 = ld_b32(&sBl[cn][cA    ]);
            const uint32_t bl1 = ld_b32(&sBl[cn][cA + 8]);
            MMA_BF16(acc[nt], ah0, ah1, ah2, ah3, bh0, bh1);
            MMA_BF16(acc[nt], ah0, ah1, ah2, ah3, bl0, bl1);
            MMA_BF16(acc[nt], al0, al1, al2, al3, bh0, bh1);
        }
        __syncthreads();
    }

    // epilogue -> split-K partials
    float* gp = g_part + (size_t)split * M_ROWS * NCOLS;
    const int orow = rowbase + rA;
    #pragma unroll
    for (int nt = 0; nt < 12; ++nt) {
        const int col = n0 + nt * 8 + cA;
        *reinterpret_cast<float2*>(gp + (size_t)orow * NCOLS + col) =
            make_float2(acc[nt][0], acc[nt][1]);
        *reinterpret_cast<float2*>(gp + (size_t)(orow + 8) * NCOLS + col) =
            make_float2(acc[nt][2], acc[nt][3]);
    }
}

// ---------------------------------------------------------------------------
// Split-K reduce + bias + 3-level inverse SWT (db4, periodization)
// One block per (b,n) row. Derived closed form of the reference algebra:
//   level j (step = 2^(j-1), Mlen = 336/step), strand s = t%step, m = t/step:
//     x1 = sum_k over q=(m+3-k)%Mlen even:  o[q*step+s]*RL[k] + d[q*step+s]*RH[k]
//     x2 = sum_k over q=(m+2-k)%Mlen even:  o[(q+1)*step+s]*RL[k] + d[(q+1)*step+s]*RH[k]
//     new = 0.5*(x1+x2)
// ---------------------------------------------------------------------------
__global__ void reduce_iswt(const float* __restrict__ bias, float* __restrict__ out)
{
    __shared__ float sc[4][PRED];   // sc[0] = evolving out; sc[1..3] = cD3,cD2,cD1
    const int t   = threadIdx.x;
    const int row = blockIdx.x;

    if (t < PRED) {
        #pragma unroll
        for (int band = 0; band < NBANDS; ++band) {
            float a = bias[band * PRED + t];
            const float* gp = g_part + (size_t)row * NCOLS + band * PRED + t;
            #pragma unroll
            for (int s = 0; s < SPLITS; ++s)
                a += gp[(size_t)s * M_ROWS * NCOLS];
            sc[band][t] = a;
        }
    }
    __syncthreads();

    const int steps[3] = {4, 2, 1};
    #pragma unroll
    for (int lv = 0; lv < 3; ++lv) {
        const int step = steps[lv];
        const int band = lv + 1;
        const int Mlen = PRED / step;
        float nv = 0.f;
        if (t < PRED) {
            const int s = t % step;
            const int m = t / step;
            float x1 = 0.f, x2 = 0.f;
            #pragma unroll
            for (int k = 0; k < 8; ++k) {
                int q = m + 3 - k;
                if (q >= Mlen) q -= Mlen;
                if (q < 0)     q += Mlen;
                if ((q & 1) == 0) {
                    const int idx = q * step + s;
                    x1 += sc[0][idx] * c_RL[k] + sc[band][idx] * c_RH[k];
                }
                int q2 = m + 2 - k;
                if (q2 >= Mlen) q2 -= Mlen;
                if (q2 < 0)     q2 += Mlen;
                if ((q2 & 1) == 0) {
                    const int idx2 = (q2 + 1) * step + s;
                    x2 += sc[0][idx2] * c_RL[k] + sc[band][idx2] * c_RH[k];
                }
            }
            nv = 0.5f * (x1 + x2);
        }
        __syncthreads();
        if (t < PRED) sc[0][t] = nv;
        __syncthreads();
    }

    if (t < PRED) out[(size_t)row * PRED + t] = sc[0][t];
}

// ---------------------------------------------------------------------------
extern "C" void kernel_launch(void* const* d_in, const int* in_sizes, int n_in,
                              void* d_out, int out_size)
{
    const float* X    = (const float*)d_in[0];  // (32,7,768,64) = (224, 49152)
    const float* W    = (const float*)d_in[1];  // (4, 49152, 336)
    const float* bias = (const float*)d_in[2];  // (4, 336)
    float* out        = (float*)d_out;          // (32, 7, 336)

    dim3 grid(NTILES, SPLITS);
    gemm_split<<<grid, THREADS_G>>>(X, W);
    reduce_iswt<<<M_ROWS, 352>>>(bias, out);
}

// round 5
// speedup vs baseline: 1.6989x; 1.6989x over previous
#include <cuda_runtime.h>
#include <cuda_bf16.h>
#include <cstdint>

// ---------------------------------------------------------------- constants
#define M_ROWS 224      // B*N
#define K_DIM  49152
#define PRED   336
#define NCOLS  1344

#define SPLITS    21
#define TOT_TILES 1536  // K_DIM / 32
#define BN        96
#define NT        14    // 1344/96
#define KT        32    // k per stage
#define THREADS   448   // 14 warps: 7 (m) x 2 (n), warp tile 32x48

// smem stage layout (bytes), padded strides for conflict-free ldmatrix
#define A_STRIDE 80     // 32 bf16 = 64B + 16 pad
#define B_STRIDE 208    // 96 bf16 = 192B + 16 pad
#define AH_OFF   0
#define AL_OFF   17920  // 224*80
#define BH_OFF   35840
#define BL_OFF   42496  // +32*208
#define STAGE    49152
#define SMEM_NEED (2 * STAGE)

// split-K scratch
__device__ float g_part[SPLITS * M_ROWS * NCOLS];

// db4 reconstruction filters
__constant__ float c_RL[8] = {
     0.23037781330885523f,  0.7148465705525415f,   0.6308807679295904f,
    -0.02798376941698385f, -0.18703481171888114f,  0.030841381835986965f,
     0.032883011666982945f, -0.010597401784997278f };
__constant__ float c_RH[8] = {
     0.010597401784997278f, 0.032883011666982945f, -0.030841381835986965f,
    -0.18703481171888114f,  0.02798376941698385f,   0.6308807679295904f,
    -0.7148465705525415f,   0.23037781330885523f };

// ---------------------------------------------------------------- helpers
__device__ __forceinline__ uint32_t smem_u32(const void* p) {
    uint32_t a;
    asm("{ .reg .u64 t; cvta.to.shared.u64 t, %1; cvt.u32.u64 %0, t; }"
        : "=r"(a) : "l"(p));
    return a;
}

#define LDSM_X4(r0, r1, r2, r3, addr)                                         \
    asm volatile("ldmatrix.sync.aligned.m8n8.x4.shared.b16 {%0,%1,%2,%3},[%4];" \
        : "=r"(r0), "=r"(r1), "=r"(r2), "=r"(r3) : "r"(addr))

#define LDSM_X4T(r0, r1, r2, r3, addr)                                        \
    asm volatile("ldmatrix.sync.aligned.m8n8.x4.trans.shared.b16 {%0,%1,%2,%3},[%4];" \
        : "=r"(r0), "=r"(r1), "=r"(r2), "=r"(r3) : "r"(addr))

#define MMA_BF16(C, A0, A1, A2, A3, B0, B1)                                   \
  asm volatile(                                                               \
      "mma.sync.aligned.m16n8k16.row.col.f32.bf16.bf16.f32 "                  \
      "{%0,%1,%2,%3}, {%4,%5,%6,%7}, {%8,%9}, {%0,%1,%2,%3};\n"               \
      : "+f"(C[0]), "+f"(C[1]), "+f"(C[2]), "+f"(C[3])                        \
      : "r"(A0), "r"(A1), "r"(A2), "r"(A3), "r"(B0), "r"(B1))

// two fp32 -> packed bf16x2 hi + packed bf16x2 lo
__device__ __forceinline__ void split2(float a, float b, uint32_t& H, uint32_t& L) {
    __nv_bfloat16 ha = __float2bfloat16(a), hb = __float2bfloat16(b);
    __nv_bfloat16 la = __float2bfloat16(a - __bfloat162float(ha));
    __nv_bfloat16 lb = __float2bfloat16(b - __bfloat162float(hb));
    __nv_bfloat162 ph; ph.x = ha; ph.y = hb;
    __nv_bfloat162 pl; pl.x = la; pl.y = lb;
    H = *reinterpret_cast<uint32_t*>(&ph);
    L = *reinterpret_cast<uint32_t*>(&pl);
}

// convert staged registers -> smem stage buffer (vectorized STS)
__device__ __forceinline__ void store_tile(char* st, int a_soff, const float4* fa,
                                           int b_soff0, float4 fb0,
                                           bool has1, int b_soff1, float4 fb1)
{
    uint32_t h[8], l[8];
    #pragma unroll
    for (int q = 0; q < 4; ++q) {
        split2(fa[q].x, fa[q].y, h[2*q],   l[2*q]);
        split2(fa[q].z, fa[q].w, h[2*q+1], l[2*q+1]);
    }
    *reinterpret_cast<uint4*>(st + AH_OFF + a_soff)      = make_uint4(h[0], h[1], h[2], h[3]);
    *reinterpret_cast<uint4*>(st + AH_OFF + a_soff + 16) = make_uint4(h[4], h[5], h[6], h[7]);
    *reinterpret_cast<uint4*>(st + AL_OFF + a_soff)      = make_uint4(l[0], l[1], l[2], l[3]);
    *reinterpret_cast<uint4*>(st + AL_OFF + a_soff + 16) = make_uint4(l[4], l[5], l[6], l[7]);

    uint32_t bh0, bh1, bl0, bl1;
    split2(fb0.x, fb0.y, bh0, bl0);
    split2(fb0.z, fb0.w, bh1, bl1);
    *reinterpret_cast<uint2*>(st + BH_OFF + b_soff0) = make_uint2(bh0, bh1);
    *reinterpret_cast<uint2*>(st + BL_OFF + b_soff0) = make_uint2(bl0, bl1);
    if (has1) {
        split2(fb1.x, fb1.y, bh0, bl0);
        split2(fb1.z, fb1.w, bh1, bl1);
        *reinterpret_cast<uint2*>(st + BH_OFF + b_soff1) = make_uint2(bh0, bh1);
        *reinterpret_cast<uint2*>(st + BL_OFF + b_soff1) = make_uint2(bl0, bl1);
    }
}

// ---------------------------------------------------------------------------
// GEMM: C[224,1344] = X @ Wcat  (split-K partials into g_part)
// mma.sync m16n8k16 bf16, fp32->bf16 hi/lo split (3 products), ldmatrix frags.
// A smem: [m][k] row-major (pad 80B). B smem: [k][n] (pad 208B), .trans frags.
// ---------------------------------------------------------------------------
__global__ void __launch_bounds__(THREADS, 1)
gemm_mma(const float* __restrict__ X, const float* __restrict__ W)
{
    extern __shared__ char smem[];
    const uint32_t sb = smem_u32(smem);
    const int t    = threadIdx.x;
    const int lane = t & 31;
    const int warp = t >> 5;
    const int n0   = blockIdx.x * BN;
    const int split = blockIdx.y;
    const int start = split * 73 + (split < 3 ? split : 3);
    const int count = 73 + (split < 3 ? 1 : 0);

    // ---- A producer: row = t/2, 16 k's at (t&1)*16 ----
    const int arow  = t >> 1;
    const int akoff = (t & 1) * 16;
    const float* aptr = X + (size_t)arow * K_DIM + (size_t)start * KT + akoff;
    const int a_soff = arow * A_STRIDE + akoff * 2;

    // ---- B producer: chunks of 4 cols (p) at fixed k; 768 chunks / 448 thr ----
    const int  k0r = t / 24, nc0 = t % 24;
    const int  nB0 = n0 + nc0 * 4;
    const int  band0 = nB0 / PRED, p0 = nB0 % PRED;
    const float* bptr0 = W + (size_t)band0 * K_DIM * PRED +
                         ((size_t)start * KT + k0r) * PRED + p0;
    const int b_soff0 = k0r * B_STRIDE + nc0 * 8;
    const bool has1 = (t < 320);
    const int  c1 = t + 448;
    const int  k1r = c1 / 24, nc1 = c1 % 24;
    const int  nB1 = n0 + nc1 * 4;
    const int  band1 = nB1 / PRED, p1 = nB1 % PRED;
    const float* bptr1 = W + (size_t)band1 * K_DIM * PRED +
                         ((size_t)start * KT + k1r) * PRED + p1;
    const int b_soff1 = k1r * B_STRIDE + nc1 * 8;

    // ---- consumer: warp tile 32(m) x 48(n); warps 7m x 2n ----
    const int mw = warp >> 1, nw = warp & 1;
    const int mbase = mw * 32, nbase = nw * 48;
    const int li = lane & 7, lj = lane >> 3;
    int arel[2], brel[3];
    #pragma unroll
    for (int mf = 0; mf < 2; ++mf)
        arel[mf] = (mbase + mf * 16 + (lj & 1) * 8 + li) * A_STRIDE + ((lj & 2) ? 16 : 0);
    #pragma unroll
    for (int nf = 0; nf < 3; ++nf)
        brel[nf] = (li + (lj & 1) * 8) * B_STRIDE + (nbase + nf * 16 + ((lj & 2) ? 8 : 0)) * 2;

    float acc[2][6][4];
    #pragma unroll
    for (int m = 0; m < 2; ++m)
        #pragma unroll
        for (int n = 0; n < 6; ++n)
            #pragma unroll
            for (int q = 0; q < 4; ++q) acc[m][n][q] = 0.f;

    // ---- prologue: fill stage 0 ----
    {
        float4 fa[4], fb0, fb1 = make_float4(0, 0, 0, 0);
        #pragma unroll
        for (int q = 0; q < 4; ++q)
            fa[q] = reinterpret_cast<const float4*>(aptr)[q];
        fb0 = *reinterpret_cast<const float4*>(bptr0);
        if (has1) fb1 = *reinterpret_cast<const float4*>(bptr1);
        store_tile(smem, a_soff, fa, b_soff0, fb0, has1, b_soff1, fb1);
    }
    __syncthreads();

    // ---- main loop ----
    for (int it = 0; it < count; ++it) {
        const int ss = it & 1;
        const uint32_t ab = sb + ss * STAGE;
        const bool more = (it + 1 < count);

        // prefetch next tile into registers
        float4 fa[4], fb0, fb1 = make_float4(0, 0, 0, 0);
        if (more) {
            const float* ap = aptr + (size_t)(it + 1) * KT;
            #pragma unroll
            for (int q = 0; q < 4; ++q)
                fa[q] = reinterpret_cast<const float4*>(ap)[q];
            const size_t bo = (size_t)(it + 1) * KT * PRED;
            fb0 = *reinterpret_cast<const float4*>(bptr0 + bo);
            if (has1) fb1 = *reinterpret_cast<const float4*>(bptr1 + bo);
        }

        // compute on stage ss (2 x k16)
        #pragma unroll
        for (int k16 = 0; k16 < KT; k16 += 16) {
            uint32_t ah[2][4], al[2][4];
            #pragma unroll
            for (int mf = 0; mf < 2; ++mf) {
                LDSM_X4(ah[mf][0], ah[mf][1], ah[mf][2], ah[mf][3],
                        ab + AH_OFF + arel[mf] + k16 * 2);
                LDSM_X4(al[mf][0], al[mf][1], al[mf][2], al[mf][3],
                        ab + AL_OFF + arel[mf] + k16 * 2);
            }
            #pragma unroll
            for (int nf = 0; nf < 3; ++nf) {
                uint32_t bh0, bh1, bh2, bh3, bl0, bl1, bl2, bl3;
                LDSM_X4T(bh0, bh1, bh2, bh3, ab + BH_OFF + brel[nf] + k16 * B_STRIDE);
                LDSM_X4T(bl0, bl1, bl2, bl3, ab + BL_OFF + brel[nf] + k16 * B_STRIDE);
                #pragma unroll
                for (int mf = 0; mf < 2; ++mf) {
                    MMA_BF16(acc[mf][2*nf],   ah[mf][0], ah[mf][1], ah[mf][2], ah[mf][3], bh0, bh1);
                    MMA_BF16(acc[mf][2*nf],   ah[mf][0], ah[mf][1], ah[mf][2], ah[mf][3], bl0, bl1);
                    MMA_BF16(acc[mf][2*nf],   al[mf][0], al[mf][1], al[mf][2], al[mf][3], bh0, bh1);
                    MMA_BF16(acc[mf][2*nf+1], ah[mf][0], ah[mf][1], ah[mf][2], ah[mf][3], bh2, bh3);
                    MMA_BF16(acc[mf][2*nf+1], ah[mf][0], ah[mf][1], ah[mf][2], ah[mf][3], bl2, bl3);
                    MMA_BF16(acc[mf][2*nf+1], al[mf][0], al[mf][1], al[mf][2], al[mf][3], bh2, bh3);
                }
            }
        }

        // store next tile into the other stage (consumed 2 iters ago; safe)
        if (more)
            store_tile(smem + (ss ^ 1) * STAGE, a_soff, fa, b_soff0, fb0,
                       has1, b_soff1, fb1);
        __syncthreads();
    }

    // ---- epilogue: split-K partials ----
    float* gp = g_part + (size_t)split * M_ROWS * NCOLS;
    const int rr = lane >> 2, cc = (lane & 3) * 2;
    #pragma unroll
    for (int mf = 0; mf < 2; ++mf) {
        const int row = mbase + mf * 16 + rr;
        #pragma unroll
        for (int ns = 0; ns < 6; ++ns) {
            const int col = n0 + nbase + ns * 8 + cc;
            *reinterpret_cast<float2*>(gp + (size_t)row * NCOLS + col) =
                make_float2(acc[mf][ns][0], acc[mf][ns][1]);
            *reinterpret_cast<float2*>(gp + (size_t)(row + 8) * NCOLS + col) =
                make_float2(acc[mf][ns][2], acc[mf][ns][3]);
        }
    }
}

// ---------------------------------------------------------------------------
// Split-K reduce + bias + 3-level inverse SWT (db4, periodization)
// ---------------------------------------------------------------------------
__global__ void reduce_iswt(const float* __restrict__ bias, float* __restrict__ out)
{
    __shared__ float sc[4][PRED];
    const int t   = threadIdx.x;
    const int row = blockIdx.x;

    if (t < PRED) {
        #pragma unroll
        for (int band = 0; band < 4; ++band) {
            float a = bias[band * PRED + t];
            const float* gp = g_part + (size_t)row * NCOLS + band * PRED + t;
            #pragma unroll
            for (int s = 0; s < SPLITS; ++s)
                a += gp[(size_t)s * M_ROWS * NCOLS];
            sc[band][t] = a;
        }
    }
    __syncthreads();

    const int steps[3] = {4, 2, 1};
    #pragma unroll
    for (int lv = 0; lv < 3; ++lv) {
        const int step = steps[lv];
        const int band = lv + 1;
        const int Mlen = PRED / step;
        float nv = 0.f;
        if (t < PRED) {
            const int s = t % step;
            const int m = t / step;
            float x1 = 0.f, x2 = 0.f;
            #pragma unroll
            for (int k = 0; k < 8; ++k) {
                int q = m + 3 - k;
                if (q >= Mlen) q -= Mlen;
                if (q < 0)     q += Mlen;
                if ((q & 1) == 0) {
                    const int idx = q * step + s;
                    x1 += sc[0][idx] * c_RL[k] + sc[band][idx] * c_RH[k];
                }
                int q2 = m + 2 - k;
                if (q2 >= Mlen) q2 -= Mlen;
                if (q2 < 0)     q2 += Mlen;
                if ((q2 & 1) == 0) {
                    const int idx2 = (q2 + 1) * step + s;
                    x2 += sc[0][idx2] * c_RL[k] + sc[band][idx2] * c_RH[k];
                }
            }
            nv = 0.5f * (x1 + x2);
        }
        __syncthreads();
        if (t < PRED) sc[0][t] = nv;
        __syncthreads();
    }

    if (t < PRED) out[(size_t)row * PRED + t] = sc[0][t];
}

// ---------------------------------------------------------------------------
extern "C" void kernel_launch(void* const* d_in, const int* in_sizes, int n_in,
                              void* d_out, int out_size)
{
    const float* X    = (const float*)d_in[0];  // (224, 49152)
    const float* W    = (const float*)d_in[1];  // (4, 49152, 336)
    const float* bias = (const float*)d_in[2];  // (4, 336)
    float* out        = (float*)d_out;          // (224, 336)

    cudaFuncSetAttribute(gemm_mma, cudaFuncAttributeMaxDynamicSharedMemorySize,
                         SMEM_NEED);
    dim3 grid(NT, SPLITS);          // 14 x 21 = 294 CTAs ~= 2 full waves
    gemm_mma<<<grid, THREADS, SMEM_NEED>>>(X, W);
    reduce_iswt<<<M_ROWS, 352>>>(bias, out);
}

// round 6
// speedup vs baseline: 2.2057x; 1.2984x over previous
#include <cuda_runtime.h>
#include <cuda_bf16.h>
#include <cstdint>

// ---------------------------------------------------------------- constants
#define M_ROWS 224      // B*N
#define K_DIM  49152
#define PRED   336
#define NCOLS  1344

#define SPLITS    21
#define BN        96
#define NT        14    // 1344/96
#define KT        64    // k per stage
#define THREADS   448   // 14 warps: 7 (m) x 2 (n), warp tile 32x48
#define K64_TOT   768   // K_DIM/64

// smem stage layout (bytes), padded strides for conflict-free ldmatrix
#define A_STRIDE 144    // 64 bf16 = 128B + 16 pad
#define B_STRIDE 208    // 96 bf16 = 192B + 16 pad
#define AH_OFF   0
#define AL_OFF   32256  // 224*144
#define BH_OFF   64512
#define BL_OFF   77824  // +64*208
#define STAGE    91136
#define SMEM_NEED (2 * STAGE)

// scratch
__device__ float g_part[SPLITS * M_ROWS * NCOLS];
__device__ __nv_bfloat16 g_XH[(size_t)M_ROWS * K_DIM];
__device__ __nv_bfloat16 g_XL[(size_t)M_ROWS * K_DIM];

// db4 reconstruction filters
__constant__ float c_RL[8] = {
     0.23037781330885523f,  0.7148465705525415f,   0.6308807679295904f,
    -0.02798376941698385f, -0.18703481171888114f,  0.030841381835986965f,
     0.032883011666982945f, -0.010597401784997278f };
__constant__ float c_RH[8] = {
     0.010597401784997278f, 0.032883011666982945f, -0.030841381835986965f,
    -0.18703481171888114f,  0.02798376941698385f,   0.6308807679295904f,
    -0.7148465705525415f,   0.23037781330885523f };

// ---------------------------------------------------------------- helpers
__device__ __forceinline__ uint32_t smem_u32(const void* p) {
    uint32_t a;
    asm("{ .reg .u64 t; cvta.to.shared.u64 t, %1; cvt.u32.u64 %0, t; }"
        : "=r"(a) : "l"(p));
    return a;
}

#define CP_ASYNC16(saddr, gptr)                                               \
    asm volatile("cp.async.cg.shared.global [%0], [%1], 16;"                  \
        :: "r"(saddr), "l"(gptr))
#define CP_COMMIT() asm volatile("cp.async.commit_group;" ::: "memory")
#define CP_WAIT0()  asm volatile("cp.async.wait_group 0;" ::: "memory")

#define LDSM_X4(r0, r1, r2, r3, addr)                                         \
    asm volatile("ldmatrix.sync.aligned.m8n8.x4.shared.b16 {%0,%1,%2,%3},[%4];" \
        : "=r"(r0), "=r"(r1), "=r"(r2), "=r"(r3) : "r"(addr))

#define LDSM_X4T(r0, r1, r2, r3, addr)                                        \
    asm volatile("ldmatrix.sync.aligned.m8n8.x4.trans.shared.b16 {%0,%1,%2,%3},[%4];" \
        : "=r"(r0), "=r"(r1), "=r"(r2), "=r"(r3) : "r"(addr))

#define MMA_BF16(C, A0, A1, A2, A3, B0, B1)                                   \
  asm volatile(                                                               \
      "mma.sync.aligned.m16n8k16.row.col.f32.bf16.bf16.f32 "                  \
      "{%0,%1,%2,%3}, {%4,%5,%6,%7}, {%8,%9}, {%0,%1,%2,%3};\n"               \
      : "+f"(C[0]), "+f"(C[1]), "+f"(C[2]), "+f"(C[3])                        \
      : "r"(A0), "r"(A1), "r"(A2), "r"(A3), "r"(B0), "r"(B1))

__device__ __forceinline__ void split2(float a, float b, uint32_t& H, uint32_t& L) {
    __nv_bfloat16 ha = __float2bfloat16(a), hb = __float2bfloat16(b);
    __nv_bfloat16 la = __float2bfloat16(a - __bfloat162float(ha));
    __nv_bfloat16 lb = __float2bfloat16(b - __bfloat162float(hb));
    __nv_bfloat162 ph; ph.x = ha; ph.y = hb;
    __nv_bfloat162 pl; pl.x = la; pl.y = lb;
    H = *reinterpret_cast<uint32_t*>(&ph);
    L = *reinterpret_cast<uint32_t*>(&pl);
}

// ---------------------------------------------------------------------------
// Pre-pass: X fp32 -> XH/XL bf16 (done ONCE; removes 14x-redundant in-loop
// conversion from the GEMM)
// ---------------------------------------------------------------------------
__global__ void __launch_bounds__(256) split_x(const float* __restrict__ X)
{
    const size_t i = ((size_t)blockIdx.x * 256 + threadIdx.x) * 4;
    const float4 v = *reinterpret_cast<const float4*>(X + i);
    uint32_t h0, h1, l0, l1;
    split2(v.x, v.y, h0, l0);
    split2(v.z, v.w, h1, l1);
    *reinterpret_cast<uint2*>(g_XH + i) = make_uint2(h0, h1);
    *reinterpret_cast<uint2*>(g_XL + i) = make_uint2(l0, l1);
}

// ---------------------------------------------------------------------------
// GEMM: C[224,1344] = X @ Wcat  (split-K partials into g_part)
// A: pre-split bf16 hi/lo via cp.async. B: fp32 LDG + in-loop split.
// mma.sync m16n8k16 bf16, 3 products (hh, hl, lh), fp32 accum.
// ---------------------------------------------------------------------------
__global__ void __launch_bounds__(THREADS, 1)
gemm_mma(const float* __restrict__ W)
{
    extern __shared__ char smem[];
    const uint32_t sb = smem_u32(smem);
    const int t    = threadIdx.x;
    const int lane = t & 31;
    const int warp = t >> 5;
    const int n0   = blockIdx.x * BN;
    const int split = blockIdx.y;
    // 768 k64-tiles over 21 splits: first 12 get 37, rest 36
    const int start = split * 36 + (split < 12 ? split : 12);
    const int count = 36 + (split < 12 ? 1 : 0);

    // ---- A producer: 3584 16B-chunks (224 rows x 8 kc x 2 mats), 8/thread
    const __nv_bfloat16* agp[8];
    uint32_t asoff[8];
    #pragma unroll
    for (int i = 0; i < 8; ++i) {
        int c = t + i * THREADS;            // 0..3583
        int mat = c >> 11;                  // c / 2048? no: 1792 per mat
        mat = c / 1792;
        int rem = c - mat * 1792;
        int row = rem >> 3;
        int kc  = rem & 7;
        const __nv_bfloat16* base = mat ? g_XL : g_XH;
        agp[i] = base + (size_t)row * K_DIM + (size_t)start * KT + kc * 8;
        asoff[i] = (mat ? AL_OFF : AH_OFF) + row * A_STRIDE + kc * 16;
    }

    // ---- B producer: 1536 4-col chunks (64 k x 24), <=4/thread
    const float* bgp[4];
    uint32_t bsoff[4];
    bool bval[4];
    #pragma unroll
    for (int i = 0; i < 4; ++i) {
        int c = t + i * THREADS;
        bval[i] = (c < 64 * 24);
        int cc = bval[i] ? c : 0;
        int krow = cc / 24, nc = cc - krow * 24;
        int nB = n0 + nc * 4;
        int band = nB / PRED, p = nB - band * PRED;
        bgp[i] = W + (size_t)band * K_DIM * PRED +
                 ((size_t)start * KT + krow) * PRED + p;
        bsoff[i] = krow * B_STRIDE + nc * 8;
    }

    // ---- consumer: warp tile 32(m) x 48(n); warps 7m x 2n ----
    const int mw = warp >> 1, nw = warp & 1;
    const int mbase = mw * 32, nbase = nw * 48;
    const int li = lane & 7, lj = lane >> 3;
    int arel[2], brel[3];
    #pragma unroll
    for (int mf = 0; mf < 2; ++mf)
        arel[mf] = (mbase + mf * 16 + (lj & 1) * 8 + li) * A_STRIDE + ((lj & 2) ? 16 : 0);
    #pragma unroll
    for (int nf = 0; nf < 3; ++nf)
        brel[nf] = (li + (lj & 1) * 8) * B_STRIDE + (nbase + nf * 16 + ((lj & 2) ? 8 : 0)) * 2;

    float acc[2][6][4];
    #pragma unroll
    for (int m = 0; m < 2; ++m)
        #pragma unroll
        for (int n = 0; n < 6; ++n)
            #pragma unroll
            for (int q = 0; q < 4; ++q) acc[m][n][q] = 0.f;

    // ---- prologue: fill stage 0 ----
    {
        #pragma unroll
        for (int i = 0; i < 8; ++i)
            CP_ASYNC16(sb + asoff[i], agp[i]);
        CP_COMMIT();
        float4 fb[4];
        #pragma unroll
        for (int i = 0; i < 4; ++i)
            fb[i] = bval[i] ? *reinterpret_cast<const float4*>(bgp[i])
                            : make_float4(0, 0, 0, 0);
        #pragma unroll
        for (int i = 0; i < 4; ++i) {
            if (!bval[i]) continue;
            uint32_t h0, h1, l0, l1;
            split2(fb[i].x, fb[i].y, h0, l0);
            split2(fb[i].z, fb[i].w, h1, l1);
            *reinterpret_cast<uint2*>(smem + BH_OFF + bsoff[i]) = make_uint2(h0, h1);
            *reinterpret_cast<uint2*>(smem + BL_OFF + bsoff[i]) = make_uint2(l0, l1);
        }
        CP_WAIT0();
        __syncthreads();
    }

    // ---- main loop ----
    for (int it = 0; it < count; ++it) {
        const int ss = it & 1;
        const uint32_t ab = sb + ss * STAGE;
        const bool more = (it + 1 < count);

        float4 fb[4];
        if (more) {
            const uint32_t nsb = sb + (ss ^ 1) * STAGE;
            const size_t ao = (size_t)(it + 1) * KT;       // bf16 elems
            #pragma unroll
            for (int i = 0; i < 8; ++i)
                CP_ASYNC16(nsb + asoff[i], agp[i] + ao);
            CP_COMMIT();
            const size_t bo = (size_t)(it + 1) * KT * PRED;
            #pragma unroll
            for (int i = 0; i < 4; ++i)
                fb[i] = bval[i] ? *reinterpret_cast<const float4*>(bgp[i] + bo)
                                : make_float4(0, 0, 0, 0);
        }

        // compute on stage ss: 4 x k16
        #pragma unroll
        for (int k16 = 0; k16 < KT; k16 += 16) {
            uint32_t ah[2][4], al[2][4];
            #pragma unroll
            for (int mf = 0; mf < 2; ++mf) {
                LDSM_X4(ah[mf][0], ah[mf][1], ah[mf][2], ah[mf][3],
                        ab + AH_OFF + arel[mf] + k16 * 2);
                LDSM_X4(al[mf][0], al[mf][1], al[mf][2], al[mf][3],
                        ab + AL_OFF + arel[mf] + k16 * 2);
            }
            #pragma unroll
            for (int nf = 0; nf < 3; ++nf) {
                uint32_t bh0, bh1, bh2, bh3, bl0, bl1, bl2, bl3;
                LDSM_X4T(bh0, bh1, bh2, bh3, ab + BH_OFF + brel[nf] + k16 * B_STRIDE);
                LDSM_X4T(bl0, bl1, bl2, bl3, ab + BL_OFF + brel[nf] + k16 * B_STRIDE);
                #pragma unroll
                for (int mf = 0; mf < 2; ++mf) {
                    MMA_BF16(acc[mf][2*nf],   ah[mf][0], ah[mf][1], ah[mf][2], ah[mf][3], bh0, bh1);
                    MMA_BF16(acc[mf][2*nf],   ah[mf][0], ah[mf][1], ah[mf][2], ah[mf][3], bl0, bl1);
                    MMA_BF16(acc[mf][2*nf],   al[mf][0], al[mf][1], al[mf][2], al[mf][3], bh0, bh1);
                    MMA_BF16(acc[mf][2*nf+1], ah[mf][0], ah[mf][1], ah[mf][2], ah[mf][3], bh2, bh3);
                    MMA_BF16(acc[mf][2*nf+1], ah[mf][0], ah[mf][1], ah[mf][2], ah[mf][3], bl2, bl3);
                    MMA_BF16(acc[mf][2*nf+1], al[mf][0], al[mf][1], al[mf][2], al[mf][3], bh2, bh3);
                }
            }
        }

        if (more) {
            char* nst = smem + (ss ^ 1) * STAGE;
            #pragma unroll
            for (int i = 0; i < 4; ++i) {
                if (!bval[i]) continue;
                uint32_t h0, h1, l0, l1;
                split2(fb[i].x, fb[i].y, h0, l0);
                split2(fb[i].z, fb[i].w, h1, l1);
                *reinterpret_cast<uint2*>(nst + BH_OFF + bsoff[i]) = make_uint2(h0, h1);
                *reinterpret_cast<uint2*>(nst + BL_OFF + bsoff[i]) = make_uint2(l0, l1);
            }
            CP_WAIT0();
        }
        __syncthreads();
    }

    // ---- epilogue: split-K partials ----
    float* gp = g_part + (size_t)split * M_ROWS * NCOLS;
    const int rr = lane >> 2, cc = (lane & 3) * 2;
    #pragma unroll
    for (int mf = 0; mf < 2; ++mf) {
        const int row = mbase + mf * 16 + rr;
        #pragma unroll
        for (int ns = 0; ns < 6; ++ns) {
            const int col = n0 + nbase + ns * 8 + cc;
            *reinterpret_cast<float2*>(gp + (size_t)row * NCOLS + col) =
                make_float2(acc[mf][ns][0], acc[mf][ns][1]);
            *reinterpret_cast<float2*>(gp + (size_t)(row + 8) * NCOLS + col) =
                make_float2(acc[mf][ns][2], acc[mf][ns][3]);
        }
    }
}

// ---------------------------------------------------------------------------
// Split-K reduce + bias + 3-level inverse SWT (db4, periodization)
// ---------------------------------------------------------------------------
__global__ void reduce_iswt(const float* __restrict__ bias, float* __restrict__ out)
{
    __shared__ float sc[4][PRED];
    const int t   = threadIdx.x;
    const int row = blockIdx.x;

    if (t < PRED) {
        #pragma unroll
        for (int band = 0; band < 4; ++band) {
            float a = bias[band * PRED + t];
            const float* gp = g_part + (size_t)row * NCOLS + band * PRED + t;
            #pragma unroll
            for (int s = 0; s < SPLITS; ++s)
                a += gp[(size_t)s * M_ROWS * NCOLS];
            sc[band][t] = a;
        }
    }
    __syncthreads();

    const int steps[3] = {4, 2, 1};
    #pragma unroll
    for (int lv = 0; lv < 3; ++lv) {
        const int step = steps[lv];
        const int band = lv + 1;
        const int Mlen = PRED / step;
        float nv = 0.f;
        if (t < PRED) {
            const int s = t % step;
            const int m = t / step;
            float x1 = 0.f, x2 = 0.f;
            #pragma unroll
            for (int k = 0; k < 8; ++k) {
                int q = m + 3 - k;
                if (q >= Mlen) q -= Mlen;
                if (q < 0)     q += Mlen;
                if ((q & 1) == 0) {
                    const int idx = q * step + s;
                    x1 += sc[0][idx] * c_RL[k] + sc[band][idx] * c_RH[k];
                }
                int q2 = m + 2 - k;
                if (q2 >= Mlen) q2 -= Mlen;
                if (q2 < 0)     q2 += Mlen;
                if ((q2 & 1) == 0) {
                    const int idx2 = (q2 + 1) * step + s;
                    x2 += sc[0][idx2] * c_RL[k] + sc[band][idx2] * c_RH[k];
                }
            }
            nv = 0.5f * (x1 + x2);
        }
        __syncthreads();
        if (t < PRED) sc[0][t] = nv;
        __syncthreads();
    }

    if (t < PRED) out[(size_t)row * PRED + t] = sc[0][t];
}

// ---------------------------------------------------------------------------
extern "C" void kernel_launch(void* const* d_in, const int* in_sizes, int n_in,
                              void* d_out, int out_size)
{
    const float* X    = (const float*)d_in[0];  // (224, 49152)
    const float* W    = (const float*)d_in[1];  // (4, 49152, 336)
    const float* bias = (const float*)d_in[2];  // (4, 336)
    float* out        = (float*)d_out;          // (224, 336)

    cudaFuncSetAttribute(gemm_mma, cudaFuncAttributeMaxDynamicSharedMemorySize,
                         SMEM_NEED);
    split_x<<<(M_ROWS * K_DIM) / (256 * 4), 256>>>(X);
    dim3 grid(NT, SPLITS);          // 14 x 21 = 294 CTAs ~= 2 full waves
    gemm_mma<<<grid, THREADS, SMEM_NEED>>>(W);
    reduce_iswt<<<M_ROWS, 352>>>(bias, out);
}